// round 1
// baseline (speedup 1.0000x reference)
#include <cuda_runtime.h>
#include <cstdint>
#include <math.h>

#define Bn  128
#define Tn  512
#define En  256
#define Hn  1024
#define FHn 4096
#define Vn  128

// ---- device scratch (static __device__ arrays: allowed; no runtime allocs) ----
__device__ float g_embW[Vn * FHn];                    // 2 MB   : emb@W + b
__device__ float g_h[2][Bn * Hn];                     // 1 MB   : h ping-pong
__device__ float g_c[Bn * Hn];                        // 0.5 MB : cell state (in-place, owner-exclusive)
__device__ float g_states[(size_t)Bn * Tn * Hn];      // 256 MB : all h_t (decoder input)

// ============================================================
// init: zero h0 and c0 (must run every launch; deterministic)
// ============================================================
__global__ void init_kernel() {
    int i = blockIdx.x * blockDim.x + threadIdx.x;   // grid covers Bn*Hn/4 float4s
    float4 z = make_float4(0.f, 0.f, 0.f, 0.f);
    reinterpret_cast<float4*>(g_h[0])[i] = z;
    reinterpret_cast<float4*>(g_c)[i]    = z;
}

// ============================================================
// embW[v][f] = sum_e emb[v][e] * W[e][f] + b[f]
// grid 128 = (16 v-blocks of 8) x (8 f-blocks of 512); block 128 threads
// ============================================================
__global__ __launch_bounds__(128) void embw_kernel(const float* __restrict__ emb,
                                                   const float* __restrict__ W,
                                                   const float* __restrict__ bias) {
    __shared__ float es[8][En];
    int tid = threadIdx.x;
    int fb  = blockIdx.x & 7;
    int vb  = blockIdx.x >> 3;

    #pragma unroll
    for (int i = 0; i < 16; i++) {
        int idx = i * 128 + tid;
        int vl = idx >> 8, e = idx & 255;
        es[vl][e] = emb[(vb * 8 + vl) * En + e];
    }
    __syncthreads();

    int f0 = fb * 512 + tid * 4;
    float acc[8][4];
    #pragma unroll
    for (int v = 0; v < 8; v++)
        #pragma unroll
        for (int c = 0; c < 4; c++) acc[v][c] = 0.f;

    for (int e = 0; e < En; e++) {
        float4 w4 = *reinterpret_cast<const float4*>(&W[e * FHn + f0]);
        #pragma unroll
        for (int v = 0; v < 8; v++) {
            float a = es[v][e];
            acc[v][0] += a * w4.x;
            acc[v][1] += a * w4.y;
            acc[v][2] += a * w4.z;
            acc[v][3] += a * w4.w;
        }
    }
    float4 b4 = *reinterpret_cast<const float4*>(&bias[f0]);
    #pragma unroll
    for (int v = 0; v < 8; v++) {
        float4 r;
        r.x = acc[v][0] + b4.x; r.y = acc[v][1] + b4.y;
        r.z = acc[v][2] + b4.z; r.w = acc[v][3] + b4.w;
        *reinterpret_cast<float4*>(&g_embW[(vb * 8 + v) * FHn + f0]) = r;
    }
}

// ============================================================
// One LSTM time step.
// grid 128 CTAs: CTA cid owns units [cid*8, cid*8+8) -> z cols {g*1024+u}.
// block 256 threads: thread = (rowg 0..31 [4 batch rows each], uloc 0..7).
// Computes Z[128 x 32] = h_cur(128x1024) @ U[:, cols], adds embW lookup,
// applies gates + mask, updates c in place, writes h to the other buffer
// and into g_states[:, t, :].
// ============================================================
__global__ __launch_bounds__(256) void lstm_step_kernel(const float* __restrict__ U,
                                                        const int* __restrict__ tokens,
                                                        int t) {
    __shared__ __align__(16) float hsm[32][132];   // [kk][b], padded stride
    __shared__ __align__(16) float usm[32][32];    // [kk][uloc*4+gate]

    const float* __restrict__ h_cur = g_h[t & 1];
    float* __restrict__       h_nxt = g_h[(t + 1) & 1];

    int tid  = threadIdx.x, cid = blockIdx.x;
    int rowg = tid >> 3;          // 0..31
    int uloc = tid & 7;           // 0..7
    int r0   = rowg * 4;
    int u    = cid * 8 + uloc;

    float acc[4][4];
    #pragma unroll
    for (int r = 0; r < 4; r++)
        #pragma unroll
        for (int c = 0; c < 4; c++) acc[r][c] = 0.f;

    for (int k0 = 0; k0 < Hn; k0 += 32) {
        __syncthreads();
        // stage h chunk transposed: hsm[kk][b] = h_cur[b][k0+kk]
        #pragma unroll
        for (int i = 0; i < 4; i++) {
            int idx = i * 256 + tid;
            int b  = idx & 127;
            int kq = idx >> 7;                 // 0..7
            float4 v = *reinterpret_cast<const float4*>(&h_cur[b * Hn + k0 + kq * 4]);
            hsm[kq * 4 + 0][b] = v.x;
            hsm[kq * 4 + 1][b] = v.y;
            hsm[kq * 4 + 2][b] = v.z;
            hsm[kq * 4 + 3][b] = v.w;
        }
        // stage U chunk, gate-interleaved: usm[kk][ul*4+g] = U[k0+kk][g*1024 + cid*8 + ul]
        #pragma unroll
        for (int i = 0; i < 4; i++) {
            int idx = i * 256 + tid;
            int kk = idx >> 5, j = idx & 31;
            usm[kk][j] = U[(k0 + kk) * FHn + (j & 3) * Hn + cid * 8 + (j >> 2)];
        }
        __syncthreads();

        #pragma unroll 8
        for (int kk = 0; kk < 32; kk++) {
            float4 a  = *reinterpret_cast<const float4*>(&hsm[kk][r0]);
            float4 b4 = *reinterpret_cast<const float4*>(&usm[kk][uloc * 4]);
            acc[0][0] += a.x * b4.x; acc[0][1] += a.x * b4.y; acc[0][2] += a.x * b4.z; acc[0][3] += a.x * b4.w;
            acc[1][0] += a.y * b4.x; acc[1][1] += a.y * b4.y; acc[1][2] += a.y * b4.z; acc[1][3] += a.y * b4.w;
            acc[2][0] += a.z * b4.x; acc[2][1] += a.z * b4.y; acc[2][2] += a.z * b4.z; acc[2][3] += a.z * b4.w;
            acc[3][0] += a.w * b4.x; acc[3][1] += a.w * b4.y; acc[3][2] += a.w * b4.z; acc[3][3] += a.w * b4.w;
        }
    }

    // epilogue: xz add + gates + mask + state update (all CTA-local for unit u)
    #pragma unroll
    for (int r = 0; r < 4; r++) {
        int b   = r0 + r;
        int tok = tokens[b * Tn + t];
        const float* ew = &g_embW[tok * FHn];
        float zi = acc[r][0] + ew[u];
        float zf = acc[r][1] + ew[Hn + u];
        float zg = acc[r][2] + ew[2 * Hn + u];
        float zo = acc[r][3] + ew[3 * Hn + u];

        float ig = 1.f / (1.f + expf(-zi));
        float fg = 1.f / (1.f + expf(-zf));
        float gg = tanhf(zg);
        float og = 1.f / (1.f + expf(-zo));

        float c_old = g_c[b * Hn + u];
        float c_new = fg * c_old + ig * gg;
        float h_new = og * tanhf(c_new);

        bool  m     = (tok != 0);
        float h_old = h_cur[b * Hn + u];
        float h_out = m ? h_new : h_old;
        float c_out = m ? c_new : c_old;

        g_c[b * Hn + u]       = c_out;
        h_nxt[b * Hn + u]     = h_out;
        g_states[((size_t)b * Tn + t) * Hn + u] = h_out;
    }
}

// ============================================================
// logits = states @ Wd + bd ; softmax over V=128; fused per 64-row tile.
// grid 1024 (64 rows each), block 512; thread tile 4x4.
// ============================================================
__global__ __launch_bounds__(512) void logits_softmax_kernel(const float* __restrict__ Wd,
                                                             const float* __restrict__ bd,
                                                             float* __restrict__ out) {
    __shared__ __align__(16) float buf[64 * 132];   // staging overlaid with logits tile
    float* ssm = buf;                // [32][68]  states chunk (k-major)
    float* wsm = buf + 32 * 68;      // [32][128] Wd chunk

    int tid  = threadIdx.x;
    size_t R0 = (size_t)blockIdx.x * 64;
    int rowg = tid & 15;             // 16 x 4 = 64 rows
    int colg = tid >> 4;             // 32 x 4 = 128 cols

    float acc[4][4];
    #pragma unroll
    for (int r = 0; r < 4; r++)
        #pragma unroll
        for (int c = 0; c < 4; c++) acc[r][c] = 0.f;

    for (int k0 = 0; k0 < Hn; k0 += 32) {
        __syncthreads();
        {   // stage states: thread -> (row 0..63, kq 0..7)
            int row = tid & 63, kq = tid >> 6;
            float4 v = *reinterpret_cast<const float4*>(&g_states[(R0 + row) * Hn + k0 + kq * 4]);
            ssm[(kq * 4 + 0) * 68 + row] = v.x;
            ssm[(kq * 4 + 1) * 68 + row] = v.y;
            ssm[(kq * 4 + 2) * 68 + row] = v.z;
            ssm[(kq * 4 + 3) * 68 + row] = v.w;
        }
        #pragma unroll
        for (int i = 0; i < 8; i++) {
            int idx = i * 512 + tid;
            int kk = idx >> 7, col = idx & 127;
            wsm[kk * 128 + col] = Wd[(k0 + kk) * Vn + col];
        }
        __syncthreads();

        #pragma unroll 8
        for (int kk = 0; kk < 32; kk++) {
            float4 a  = *reinterpret_cast<const float4*>(&ssm[kk * 68 + rowg * 4]);
            float4 b4 = *reinterpret_cast<const float4*>(&wsm[kk * 128 + colg * 4]);
            acc[0][0] += a.x * b4.x; acc[0][1] += a.x * b4.y; acc[0][2] += a.x * b4.z; acc[0][3] += a.x * b4.w;
            acc[1][0] += a.y * b4.x; acc[1][1] += a.y * b4.y; acc[1][2] += a.y * b4.z; acc[1][3] += a.y * b4.w;
            acc[2][0] += a.z * b4.x; acc[2][1] += a.z * b4.y; acc[2][2] += a.z * b4.z; acc[2][3] += a.z * b4.w;
            acc[3][0] += a.w * b4.x; acc[3][1] += a.w * b4.y; acc[3][2] += a.w * b4.z; acc[3][3] += a.w * b4.w;
        }
    }

    __syncthreads();   // all staging reads done; reuse buf as logits tile
    float4 bd4 = *reinterpret_cast<const float4*>(&bd[colg * 4]);
    #pragma unroll
    for (int r = 0; r < 4; r++) {
        buf[(rowg * 4 + r) * 132 + colg * 4 + 0] = acc[r][0] + bd4.x;
        buf[(rowg * 4 + r) * 132 + colg * 4 + 1] = acc[r][1] + bd4.y;
        buf[(rowg * 4 + r) * 132 + colg * 4 + 2] = acc[r][2] + bd4.z;
        buf[(rowg * 4 + r) * 132 + colg * 4 + 3] = acc[r][3] + bd4.w;
    }
    __syncthreads();

    // softmax: 16 warps x 4 rows
    int w = tid >> 5, lane = tid & 31;
    #pragma unroll
    for (int rr = 0; rr < 4; rr++) {
        int row = w * 4 + rr;
        float4 x = *reinterpret_cast<const float4*>(&buf[row * 132 + lane * 4]);
        float m = fmaxf(fmaxf(x.x, x.y), fmaxf(x.z, x.w));
        #pragma unroll
        for (int o = 16; o > 0; o >>= 1) m = fmaxf(m, __shfl_xor_sync(0xffffffff, m, o));
        float4 e;
        e.x = expf(x.x - m); e.y = expf(x.y - m);
        e.z = expf(x.z - m); e.w = expf(x.w - m);
        float s = e.x + e.y + e.z + e.w;
        #pragma unroll
        for (int o = 16; o > 0; o >>= 1) s += __shfl_xor_sync(0xffffffff, s, o);
        float inv = 1.f / s;
        e.x *= inv; e.y *= inv; e.z *= inv; e.w *= inv;
        *reinterpret_cast<float4*>(&out[(R0 + row) * Vn + lane * 4]) = e;
    }
}

// ============================================================
// launcher
// ============================================================
extern "C" void kernel_launch(void* const* d_in, const int* in_sizes, int n_in,
                              void* d_out, int out_size) {
    const int*   tokens = (const int*)  d_in[0];
    const float* emb    = (const float*)d_in[1];
    const float* W      = (const float*)d_in[2];
    const float* U      = (const float*)d_in[3];
    const float* bias   = (const float*)d_in[4];
    const float* Wd     = (const float*)d_in[5];
    const float* bd     = (const float*)d_in[6];
    float*       out    = (float*)d_out;
    (void)in_sizes; (void)n_in; (void)out_size;

    init_kernel<<<(Bn * Hn / 4) / 256, 256>>>();
    embw_kernel<<<128, 128>>>(emb, W, bias);
    for (int t = 0; t < Tn; t++)
        lstm_step_kernel<<<128, 256>>>(U, tokens, t);
    logits_softmax_kernel<<<(Bn * Tn) / 64, 512>>>(Wd, bd, out);
}

// round 3
// speedup vs baseline: 1.4967x; 1.4967x over previous
#include <cuda_runtime.h>
#include <cuda_bf16.h>
#include <cstdint>
#include <math.h>

#define Bn  128
#define Tn  512
#define En  256
#define Hn  1024
#define FHn 4096
#define Vn  128
#define KSPL 3072          // split-K: [h_hi | h_lo | h_hi] x [U_hi ; U_hi ; U_lo]

// ---------------- device scratch (static: no runtime allocs) ----------------
__device__ float g_embW[Vn * FHn];                       // emb@W + b (2 MB, L2-resident)
__device__ float g_hf[2][Bn * Hn];                       // fp32 h ping-pong
__device__ float g_c[Bn * Hn];                           // cell state
__device__ __nv_bfloat16 g_hbf[2][2][Bn * Hn];           // [buf][hi/lo] h bf16
__device__ __nv_bfloat16 g_Bpk[64][64][KSPL];            // packed U   (24 MB)
__device__ __nv_bfloat16 g_Wpk[Vn][KSPL];                // packed Wd  (768 KB)
__device__ __nv_bfloat16 g_shi[(size_t)Bn * Tn * Hn];    // states hi (128 MB)
__device__ __nv_bfloat16 g_slo[(size_t)Bn * Tn * Hn];    // states lo (128 MB)

// ---------------- helpers ----------------
__device__ __forceinline__ uint32_t smem_u32(const void* p) {
    uint32_t a;
    asm("{ .reg .u64 t; cvta.to.shared.u64 t, %1; cvt.u32.u64 %0, t; }" : "=r"(a) : "l"(p));
    return a;
}
#define CP16(dst, src)  asm volatile("cp.async.cg.shared.global [%0], [%1], 16;" :: "r"(dst), "l"(src))
#define CP_COMMIT()     asm volatile("cp.async.commit_group;" ::: "memory")
#define CP_WAIT1()      asm volatile("cp.async.wait_group 1;" ::: "memory")
#define CP_WAIT0()      asm volatile("cp.async.wait_group 0;" ::: "memory")

#define LDSM4(r, addr)                                                              \
    asm volatile("ldmatrix.sync.aligned.m8n8.x4.shared.b16 {%0,%1,%2,%3}, [%4];"    \
        : "=r"((r)[0]), "=r"((r)[1]), "=r"((r)[2]), "=r"((r)[3]) : "r"(addr))
#define LDSM2(r, addr)                                                              \
    asm volatile("ldmatrix.sync.aligned.m8n8.x2.shared.b16 {%0,%1}, [%2];"          \
        : "=r"((r)[0]), "=r"((r)[1]) : "r"(addr))
#define MMA16816(d, a, b)                                                           \
    asm volatile("mma.sync.aligned.m16n8k16.row.col.f32.bf16.bf16.f32 "             \
        "{%0,%1,%2,%3}, {%4,%5,%6,%7}, {%8,%9}, {%0,%1,%2,%3};"                     \
        : "+f"((d)[0]), "+f"((d)[1]), "+f"((d)[2]), "+f"((d)[3])                    \
        : "r"((a)[0]), "r"((a)[1]), "r"((a)[2]), "r"((a)[3]),                       \
          "r"((b)[0]), "r"((b)[1]))

// ============================================================
// init: zero h0 (fp32 + bf16 hi/lo) and c0
// ============================================================
__global__ void init_zero() {
    int i = blockIdx.x * blockDim.x + threadIdx.x;      // 32768 threads
    float4 z = make_float4(0.f, 0.f, 0.f, 0.f);
    reinterpret_cast<float4*>(g_hf[0])[i] = z;
    reinterpret_cast<float4*>(g_c)[i]     = z;
    uint4 zu = make_uint4(0u, 0u, 0u, 0u);
    reinterpret_cast<uint4*>(&g_hbf[0][0][0])[i] = zu;  // covers [0][0] and [0][1]
}

// ============================================================
// embW = emb@W + b (fp32, one-time)
// ============================================================
__global__ __launch_bounds__(128) void embw_kernel(const float* __restrict__ emb,
                                                   const float* __restrict__ W,
                                                   const float* __restrict__ bias) {
    __shared__ float es[8][En];
    int tid = threadIdx.x;
    int fb  = blockIdx.x & 7;
    int vb  = blockIdx.x >> 3;
    #pragma unroll
    for (int i = 0; i < 16; i++) {
        int idx = i * 128 + tid;
        es[idx >> 8][idx & 255] = emb[(vb * 8 + (idx >> 8)) * En + (idx & 255)];
    }
    __syncthreads();
    int f0 = fb * 512 + tid * 4;
    float acc[8][4];
    #pragma unroll
    for (int v = 0; v < 8; v++)
        #pragma unroll
        for (int c = 0; c < 4; c++) acc[v][c] = 0.f;
    for (int e = 0; e < En; e++) {
        float4 w4 = *reinterpret_cast<const float4*>(&W[e * FHn + f0]);
        #pragma unroll
        for (int v = 0; v < 8; v++) {
            float a = es[v][e];
            acc[v][0] += a * w4.x; acc[v][1] += a * w4.y;
            acc[v][2] += a * w4.z; acc[v][3] += a * w4.w;
        }
    }
    float4 b4 = *reinterpret_cast<const float4*>(&bias[f0]);
    #pragma unroll
    for (int v = 0; v < 8; v++) {
        float4 r;
        r.x = acc[v][0] + b4.x; r.y = acc[v][1] + b4.y;
        r.z = acc[v][2] + b4.z; r.w = acc[v][3] + b4.w;
        *reinterpret_cast<float4*>(&g_embW[(vb * 8 + v) * FHn + f0]) = r;
    }
}

// ============================================================
// pack B (recurrent weights): g_Bpk[cid][n][k], n = gate*16+ul,
// k-blocks: [0,1024)=U_hi  [1024,2048)=U_hi  [2048,3072)=U_lo
// ============================================================
__global__ __launch_bounds__(256) void packB_kernel(const float* __restrict__ U) {
    int cid = blockIdx.x, tid = threadIdx.x;
    int u0 = cid * 16;
    for (int i = tid; i < 64 * KSPL; i += 256) {
        int n = i / KSPL, k = i - n * KSPL;
        int kk  = (k < Hn) ? k : (k < 2 * Hn) ? k - Hn : k - 2 * Hn;
        int col = (n >> 4) * Hn + u0 + (n & 15);
        float v = U[kk * FHn + col];
        __nv_bfloat16 hi = __float2bfloat16(v);
        g_Bpk[cid][n][k] = (k < 2 * Hn) ? hi : __float2bfloat16(v - __bfloat162float(hi));
    }
}

// ============================================================
// pack Wd: g_Wpk[v][k], k-blocks [Wd_hi ; Wd_hi ; Wd_lo]
// ============================================================
__global__ __launch_bounds__(256) void packW_kernel(const float* __restrict__ Wd) {
    int tid = blockIdx.x * 256 + threadIdx.x;
    for (int i = tid; i < Vn * KSPL; i += gridDim.x * 256) {
        int v = i / KSPL, k = i - v * KSPL;
        int kk = (k < Hn) ? k : (k < 2 * Hn) ? k - Hn : k - 2 * Hn;
        float x = Wd[kk * Vn + v];
        __nv_bfloat16 hi = __float2bfloat16(x);
        g_Wpk[v][k] = (k < 2 * Hn) ? hi : __float2bfloat16(x - __bfloat162float(hi));
    }
}

// ============================================================
// LSTM step via mma.sync (HMMA bf16, fp32 acc).
// grid 64 CTAs (tile 128x64), 256 threads = 8 warps (2 x 4), warp tile 64x16.
// K = 3072 in 48 chunks of 64, cp.async double-buffered, 144B padded rows.
// ============================================================
#define ACH 18432        // per-buffer A bytes (128 rows * 144)
#define BCH 9216         // per-buffer B bytes (64 rows * 144)
#define STEP_SMEM (2 * ACH + 2 * BCH)   // 55296

__global__ __launch_bounds__(256, 1) void lstm_step_mma(const int* __restrict__ tokens, int t) {
    extern __shared__ __align__(128) char smem[];
    const uint32_t sA = smem_u32(smem);
    const uint32_t sB = sA + 2 * ACH;

    const int tid  = threadIdx.x;
    const int cid  = blockIdx.x;
    const int lane = tid & 31;
    const int wid  = tid >> 5;
    const int wm   = wid >> 2;            // 0..1
    const int wn   = wid & 3;             // 0..3
    const int cur  = t & 1, nxt = cur ^ 1;
    const int u0   = cid * 16;

    const char* Ahi = (const char*)g_hbf[cur][0];
    const char* Alo = (const char*)g_hbf[cur][1];
    const char* Bg  = (const char*)&g_Bpk[cid][0][0];

    float acc[4][2][4];
    #pragma unroll
    for (int mt = 0; mt < 4; mt++)
        #pragma unroll
        for (int nt = 0; nt < 2; nt++)
            #pragma unroll
            for (int q = 0; q < 4; q++) acc[mt][nt][q] = 0.f;

    // ldmatrix per-lane base addresses (144B row stride -> conflict-free)
    const uint32_t aBase = sA + (uint32_t)(wm * 64 + (lane & 15)) * 144 + (uint32_t)(lane >> 4) * 16;
    const uint32_t bBase = sB + (uint32_t)(wn * 16 + (lane & 7))  * 144 + (uint32_t)((lane >> 3) & 1) * 16;

    auto load_chunk = [&](int ci, int buf) {
        // A: 128 rows x 128B = 1024 x 16B
        const char* Asel = (ci < 16) ? Ahi : (ci < 32) ? Alo : Ahi;
        int koff = (ci & 15) * 128;
        #pragma unroll
        for (int i = 0; i < 4; i++) {
            int idx = i * 256 + tid;
            int row = idx >> 3, c16 = idx & 7;
            CP16(sA + buf * ACH + row * 144 + c16 * 16,
                 Asel + row * 2048 + koff + c16 * 16);
        }
        // B: 64 rows x 128B = 512 x 16B
        #pragma unroll
        for (int i = 0; i < 2; i++) {
            int idx = i * 256 + tid;
            int row = idx >> 3, c16 = idx & 7;
            CP16(sB + buf * BCH + row * 144 + c16 * 16,
                 Bg + row * (KSPL * 2) + ci * 128 + c16 * 16);
        }
        CP_COMMIT();
    };

    load_chunk(0, 0);
    for (int ci = 0; ci < 48; ci++) {
        const int buf = ci & 1;
        if (ci + 1 < 48) { load_chunk(ci + 1, buf ^ 1); CP_WAIT1(); }
        else             { CP_WAIT0(); }
        __syncthreads();

        const uint32_t a0 = aBase + buf * ACH;
        const uint32_t b0 = bBase + buf * BCH;
        #pragma unroll
        for (int kk = 0; kk < 4; kk++) {
            uint32_t ar[4][4], br[2][2];
            #pragma unroll
            for (int mt = 0; mt < 4; mt++) LDSM4(ar[mt], a0 + mt * (16 * 144) + kk * 32);
            #pragma unroll
            for (int nt = 0; nt < 2; nt++) LDSM2(br[nt], b0 + nt * (8 * 144) + kk * 32);
            #pragma unroll
            for (int mt = 0; mt < 4; mt++)
                #pragma unroll
                for (int nt = 0; nt < 2; nt++) MMA16816(acc[mt][nt], ar[mt], br[nt]);
        }
        __syncthreads();
    }

    // ---- epilogue: transpose via smem, gates, state update ----
    float* Csm = (float*)smem;            // [128][68]
    const int tg = lane >> 2, tq = lane & 3;
    #pragma unroll
    for (int mt = 0; mt < 4; mt++)
        #pragma unroll
        for (int nt = 0; nt < 2; nt++) {
            int r = wm * 64 + mt * 16 + tg;
            int c = wn * 16 + nt * 8 + tq * 2;
            Csm[r * 68 + c]           = acc[mt][nt][0];
            Csm[r * 68 + c + 1]       = acc[mt][nt][1];
            Csm[(r + 8) * 68 + c]     = acc[mt][nt][2];
            Csm[(r + 8) * 68 + c + 1] = acc[mt][nt][3];
        }
    __syncthreads();

    const int b   = tid >> 1;
    const int ulb = (tid & 1) * 8;
    const int tok = tokens[b * Tn + t];
    const bool msk = (tok != 0);
    const float* ew = g_embW + (size_t)tok * FHn;

    #pragma unroll
    for (int j = 0; j < 8; j++) {
        int ul = ulb + j, u = u0 + ul;
        float zi = Csm[b * 68 + ul]      + ew[u];
        float zf = Csm[b * 68 + 16 + ul] + ew[Hn + u];
        float zg = Csm[b * 68 + 32 + ul] + ew[2 * Hn + u];
        float zo = Csm[b * 68 + 48 + ul] + ew[3 * Hn + u];

        float ig = 1.f / (1.f + expf(-zi));
        float fg = 1.f / (1.f + expf(-zf));
        float gg = tanhf(zg);
        float og = 1.f / (1.f + expf(-zo));

        float c_old = g_c[b * Hn + u];
        float h_old = g_hf[cur][b * Hn + u];
        float c_new = fg * c_old + ig * gg;
        float h_new = og * tanhf(c_new);
        float c_out = msk ? c_new : c_old;
        float h_out = msk ? h_new : h_old;

        g_c[b * Hn + u]       = c_out;
        g_hf[nxt][b * Hn + u] = h_out;
        __nv_bfloat16 hb = __float2bfloat16(h_out);
        __nv_bfloat16 lb = __float2bfloat16(h_out - __bfloat162float(hb));
        g_hbf[nxt][0][b * Hn + u] = hb;
        g_hbf[nxt][1][b * Hn + u] = lb;
        size_t srow = ((size_t)b * Tn + t) * Hn + u;
        g_shi[srow] = hb;
        g_slo[srow] = lb;
    }
}

// ============================================================
// decoder via mma.sync: logits = states @ Wd + bd, fused softmax.
// grid 512 CTAs (tile 128 rows x 128 V), warp tile 64x32.
// ============================================================
#define DACH 18432       // A buffer (128*144)
#define DBCH 18432       // B buffer (128*144)
#define DEC_SMEM (2 * DACH + 2 * DBCH)  // 73728

__global__ __launch_bounds__(256, 1) void decoder_mma(const float* __restrict__ bd,
                                                      float* __restrict__ out) {
    extern __shared__ __align__(128) char smem[];
    const uint32_t sA = smem_u32(smem);
    const uint32_t sB = sA + 2 * DACH;

    const int tid  = threadIdx.x;
    const int lane = tid & 31;
    const int wid  = tid >> 5;
    const int wm   = wid >> 2;
    const int wn   = wid & 3;
    const size_t R0 = (size_t)blockIdx.x * 128;

    float acc[4][4][4];
    #pragma unroll
    for (int mt = 0; mt < 4; mt++)
        #pragma unroll
        for (int nt = 0; nt < 4; nt++)
            #pragma unroll
            for (int q = 0; q < 4; q++) acc[mt][nt][q] = 0.f;

    const uint32_t aBase = sA + (uint32_t)(wm * 64 + (lane & 15)) * 144 + (uint32_t)(lane >> 4) * 16;
    const uint32_t bBase = sB + (uint32_t)(wn * 32 + (lane & 7))  * 144 + (uint32_t)((lane >> 3) & 1) * 16;

    auto load_chunk = [&](int ci, int buf) {
        const char* Asel = (ci < 16) ? (const char*)g_shi
                        : (ci < 32) ? (const char*)g_slo : (const char*)g_shi;
        int koff = (ci & 15) * 128;
        #pragma unroll
        for (int i = 0; i < 4; i++) {
            int idx = i * 256 + tid;
            int row = idx >> 3, c16 = idx & 7;
            CP16(sA + buf * DACH + row * 144 + c16 * 16,
                 Asel + (R0 + row) * 2048 + koff + c16 * 16);
        }
        #pragma unroll
        for (int i = 0; i < 4; i++) {
            int idx = i * 256 + tid;
            int row = idx >> 3, c16 = idx & 7;
            CP16(sB + buf * DBCH + row * 144 + c16 * 16,
                 (const char*)&g_Wpk[0][0] + row * (KSPL * 2) + ci * 128 + c16 * 16);
        }
        CP_COMMIT();
    };

    load_chunk(0, 0);
    for (int ci = 0; ci < 48; ci++) {
        const int buf = ci & 1;
        if (ci + 1 < 48) { load_chunk(ci + 1, buf ^ 1); CP_WAIT1(); }
        else             { CP_WAIT0(); }
        __syncthreads();

        const uint32_t a0 = aBase + buf * DACH;
        const uint32_t b0 = bBase + buf * DBCH;
        #pragma unroll
        for (int kk = 0; kk < 4; kk++) {
            uint32_t ar[4][4], br[4][2];
            #pragma unroll
            for (int mt = 0; mt < 4; mt++) LDSM4(ar[mt], a0 + mt * (16 * 144) + kk * 32);
            #pragma unroll
            for (int nt = 0; nt < 4; nt++) LDSM2(br[nt], b0 + nt * (8 * 144) + kk * 32);
            #pragma unroll
            for (int mt = 0; mt < 4; mt++)
                #pragma unroll
                for (int nt = 0; nt < 4; nt++) MMA16816(acc[mt][nt], ar[mt], br[nt]);
        }
        __syncthreads();
    }

    // ---- epilogue: logits tile -> smem, bias + softmax, write out ----
    float* Csm = (float*)smem;            // [128][132]
    const int tg = lane >> 2, tq = lane & 3;
    #pragma unroll
    for (int mt = 0; mt < 4; mt++)
        #pragma unroll
        for (int nt = 0; nt < 4; nt++) {
            int r = wm * 64 + mt * 16 + tg;
            int c = wn * 32 + nt * 8 + tq * 2;
            Csm[r * 132 + c]           = acc[mt][nt][0];
            Csm[r * 132 + c + 1]       = acc[mt][nt][1];
            Csm[(r + 8) * 132 + c]     = acc[mt][nt][2];
            Csm[(r + 8) * 132 + c + 1] = acc[mt][nt][3];
        }
    __syncthreads();

    float4 bd4 = *reinterpret_cast<const float4*>(&bd[lane * 4]);
    #pragma unroll
    for (int rr = 0; rr < 16; rr++) {
        int row = wid * 16 + rr;
        float4 x = *reinterpret_cast<const float4*>(&Csm[row * 132 + lane * 4]);
        x.x += bd4.x; x.y += bd4.y; x.z += bd4.z; x.w += bd4.w;
        float m = fmaxf(fmaxf(x.x, x.y), fmaxf(x.z, x.w));
        #pragma unroll
        for (int o = 16; o > 0; o >>= 1) m = fmaxf(m, __shfl_xor_sync(0xffffffff, m, o));
        float4 e;
        e.x = expf(x.x - m); e.y = expf(x.y - m);
        e.z = expf(x.z - m); e.w = expf(x.w - m);
        float s = e.x + e.y + e.z + e.w;
        #pragma unroll
        for (int o = 16; o > 0; o >>= 1) s += __shfl_xor_sync(0xffffffff, s, o);
        float inv = 1.f / s;
        e.x *= inv; e.y *= inv; e.z *= inv; e.w *= inv;
        *reinterpret_cast<float4*>(&out[(R0 + row) * Vn + lane * 4]) = e;
    }
}

// ============================================================
// launcher
// ============================================================
extern "C" void kernel_launch(void* const* d_in, const int* in_sizes, int n_in,
                              void* d_out, int out_size) {
    const int*   tokens = (const int*)  d_in[0];
    const float* emb    = (const float*)d_in[1];
    const float* W      = (const float*)d_in[2];
    const float* U      = (const float*)d_in[3];
    const float* bias   = (const float*)d_in[4];
    const float* Wd     = (const float*)d_in[5];
    const float* bd     = (const float*)d_in[6];
    float*       out    = (float*)d_out;
    (void)in_sizes; (void)n_in; (void)out_size;

    cudaFuncSetAttribute(lstm_step_mma, cudaFuncAttributeMaxDynamicSharedMemorySize, STEP_SMEM);
    cudaFuncSetAttribute(decoder_mma,  cudaFuncAttributeMaxDynamicSharedMemorySize, DEC_SMEM);

    init_zero<<<128, 256>>>();
    embw_kernel<<<128, 128>>>(emb, W, bias);
    packB_kernel<<<64, 256>>>(U);
    packW_kernel<<<96, 256>>>(Wd);
    for (int t = 0; t < Tn; t++)
        lstm_step_mma<<<64, 256, STEP_SMEM>>>(tokens, t);
    decoder_mma<<<512, 256, DEC_SMEM>>>(bd, out);
}

// round 5
// speedup vs baseline: 3.4143x; 2.2812x over previous
#include <cuda_runtime.h>
#include <cuda_bf16.h>
#include <cstdint>
#include <math.h>

#define Bn  128
#define Tn  512
#define En  256
#define Hn  1024
#define FHn 4096
#define Vn  128
#define KSPL 3072          // decoder split-K: [hi | lo | hi] x [hi ; hi ; lo]

// ---------------- device scratch (static: no runtime allocs) ----------------
__device__ float g_embW[Vn * FHn];                       // emb@W + b (2 MB, L2-resident)
__device__ float g_hf[2][Bn * Hn];                       // fp32 h ping-pong
__device__ float g_c[Bn * Hn];                           // cell state
__device__ __nv_bfloat16 g_hbf[2][2][Bn * Hn];           // [buf][hi/lo] h bf16
__device__ __nv_bfloat16 g_Bpk[64][64][2 * Hn];          // [cid][n][k: 0..1023 hi, 1024.. lo] (16 MB)
__device__ __nv_bfloat16 g_Wpk[Vn][KSPL];                // packed Wd (768 KB)
__device__ __nv_bfloat16 g_shi[(size_t)Bn * Tn * Hn];    // states hi (128 MB)
__device__ __nv_bfloat16 g_slo[(size_t)Bn * Tn * Hn];    // states lo (128 MB)

// ---------------- helpers ----------------
__device__ __forceinline__ uint32_t smem_u32(const void* p) {
    uint32_t a;
    asm("{ .reg .u64 t; cvta.to.shared.u64 t, %1; cvt.u32.u64 %0, t; }" : "=r"(a) : "l"(p));
    return a;
}
#define CP16(dst, src)  asm volatile("cp.async.cg.shared.global [%0], [%1], 16;" :: "r"(dst), "l"(src))
#define CP_COMMIT()     asm volatile("cp.async.commit_group;" ::: "memory")
#define CP_WAIT1()      asm volatile("cp.async.wait_group 1;" ::: "memory")
#define CP_WAIT0()      asm volatile("cp.async.wait_group 0;" ::: "memory")

#define LDSM4(r, addr)                                                              \
    asm volatile("ldmatrix.sync.aligned.m8n8.x4.shared.b16 {%0,%1,%2,%3}, [%4];"    \
        : "=r"((r)[0]), "=r"((r)[1]), "=r"((r)[2]), "=r"((r)[3]) : "r"(addr))
#define LDSM2(r, addr)                                                              \
    asm volatile("ldmatrix.sync.aligned.m8n8.x2.shared.b16 {%0,%1}, [%2];"          \
        : "=r"((r)[0]), "=r"((r)[1]) : "r"(addr))
#define MMA16816(d, a, b)                                                           \
    asm volatile("mma.sync.aligned.m16n8k16.row.col.f32.bf16.bf16.f32 "             \
        "{%0,%1,%2,%3}, {%4,%5,%6,%7}, {%8,%9}, {%0,%1,%2,%3};"                     \
        : "+f"((d)[0]), "+f"((d)[1]), "+f"((d)[2]), "+f"((d)[3])                    \
        : "r"((a)[0]), "r"((a)[1]), "r"((a)[2]), "r"((a)[3]),                       \
          "r"((b)[0]), "r"((b)[1]))

// ============================================================
// init: zero h0 (fp32 + bf16 hi/lo) and c0
// ============================================================
__global__ void init_zero() {
    int i = blockIdx.x * blockDim.x + threadIdx.x;      // 32768 threads
    float4 z = make_float4(0.f, 0.f, 0.f, 0.f);
    reinterpret_cast<float4*>(g_hf[0])[i] = z;
    reinterpret_cast<float4*>(g_c)[i]     = z;
    uint4 zu = make_uint4(0u, 0u, 0u, 0u);
    reinterpret_cast<uint4*>(&g_hbf[0][0][0])[i] = zu;  // covers [0][0] and [0][1]
}

// ============================================================
// embW = emb@W + b (fp32, one-time)
// ============================================================
__global__ __launch_bounds__(128) void embw_kernel(const float* __restrict__ emb,
                                                   const float* __restrict__ W,
                                                   const float* __restrict__ bias) {
    __shared__ float es[8][En];
    int tid = threadIdx.x;
    int fb  = blockIdx.x & 7;
    int vb  = blockIdx.x >> 3;
    #pragma unroll
    for (int i = 0; i < 16; i++) {
        int idx = i * 128 + tid;
        es[idx >> 8][idx & 255] = emb[(vb * 8 + (idx >> 8)) * En + (idx & 255)];
    }
    __syncthreads();
    int f0 = fb * 512 + tid * 4;
    float acc[8][4];
    #pragma unroll
    for (int v = 0; v < 8; v++)
        #pragma unroll
        for (int c = 0; c < 4; c++) acc[v][c] = 0.f;
    for (int e = 0; e < En; e++) {
        float4 w4 = *reinterpret_cast<const float4*>(&W[e * FHn + f0]);
        #pragma unroll
        for (int v = 0; v < 8; v++) {
            float a = es[v][e];
            acc[v][0] += a * w4.x; acc[v][1] += a * w4.y;
            acc[v][2] += a * w4.z; acc[v][3] += a * w4.w;
        }
    }
    float4 b4 = *reinterpret_cast<const float4*>(&bias[f0]);
    #pragma unroll
    for (int v = 0; v < 8; v++) {
        float4 r;
        r.x = acc[v][0] + b4.x; r.y = acc[v][1] + b4.y;
        r.z = acc[v][2] + b4.z; r.w = acc[v][3] + b4.w;
        *reinterpret_cast<float4*>(&g_embW[(vb * 8 + v) * FHn + f0]) = r;
    }
}

// ============================================================
// pack B: g_Bpk[cid][n][k], n = gate*16+ul; k<1024 -> U_hi, k>=1024 -> U_lo
// ============================================================
__global__ __launch_bounds__(256) void packB_kernel(const float* __restrict__ U) {
    int cid = blockIdx.x, tid = threadIdx.x;
    int u0 = cid * 16;
    for (int i = tid; i < 64 * 2 * Hn; i += 256) {
        int n = i >> 11, k = i & (2 * Hn - 1);
        int kk  = k & (Hn - 1);
        int col = (n >> 4) * Hn + u0 + (n & 15);
        float v = U[kk * FHn + col];
        __nv_bfloat16 hi = __float2bfloat16(v);
        g_Bpk[cid][n][k] = (k < Hn) ? hi : __float2bfloat16(v - __bfloat162float(hi));
    }
}

// ============================================================
// pack Wd: g_Wpk[v][k], k-blocks [Wd_hi ; Wd_hi ; Wd_lo]
// ============================================================
__global__ __launch_bounds__(256) void packW_kernel(const float* __restrict__ Wd) {
    int tid = blockIdx.x * 256 + threadIdx.x;
    for (int i = tid; i < Vn * KSPL; i += gridDim.x * 256) {
        int v = i / KSPL, k = i - v * KSPL;
        int kk = (k < Hn) ? k : (k < 2 * Hn) ? k - Hn : k - 2 * Hn;
        float x = Wd[kk * Vn + v];
        __nv_bfloat16 hi = __float2bfloat16(x);
        g_Wpk[v][k] = (k < 2 * Hn) ? hi : __float2bfloat16(x - __bfloat162float(hi));
    }
}

// ============================================================
// LSTM step via mma.sync, full chip.
// grid 128 = 2 M-halves x 64 col-tiles. CTA tile M=64, N=64, true-K=1024.
// Per macro-chunk (K=64): stage {A_hi, A_lo, B_hi, B_lo}, issue 3 products.
// 3-stage cp.async pipeline (preload 2 groups -> CP_WAIT1 drains stage ci),
// one __syncthreads per chunk. 8 warps (2 wm x 4 wn), warp tile 32x16.
// ============================================================
#define TILE  9216                       // 64 rows * 144B
#define STG   (4 * TILE)                 // 36864
#define AHI_OFF 0
#define ALO_OFF TILE
#define BHI_OFF (2 * TILE)
#define BLO_OFF (3 * TILE)
#define STEP_SMEM (3 * STG)              // 110592

__global__ __launch_bounds__(256, 1) void lstm_step_mma(const int* __restrict__ tokens, int t) {
    extern __shared__ __align__(128) char smem[];
    const uint32_t sBuf = smem_u32(smem);

    const int tid  = threadIdx.x;
    const int mb   = blockIdx.x & 1;
    const int cid  = blockIdx.x >> 1;
    const int lane = tid & 31;
    const int wid  = tid >> 5;
    const int wm   = wid >> 2;            // 0..1
    const int wn   = wid & 3;             // 0..3
    const int cur  = t & 1, nxt = cur ^ 1;
    const int u0   = cid * 16;
    const int mrow0 = mb * 64;

    const char* Ahi = (const char*)g_hbf[cur][0];
    const char* Alo = (const char*)g_hbf[cur][1];
    const char* Bg  = (const char*)&g_Bpk[cid][0][0];

    float acc[2][2][4];
    #pragma unroll
    for (int mt = 0; mt < 2; mt++)
        #pragma unroll
        for (int nt = 0; nt < 2; nt++)
            #pragma unroll
            for (int q = 0; q < 4; q++) acc[mt][nt][q] = 0.f;

    const uint32_t aOff = (uint32_t)(wm * 32 + (lane & 15)) * 144 + (uint32_t)(lane >> 4) * 16;
    const uint32_t bOff = (uint32_t)(wn * 16 + (lane & 7))  * 144 + (uint32_t)((lane >> 3) & 1) * 16;

    auto load_chunk = [&](int ci, int stg) {
        const uint32_t S = sBuf + stg * STG;
        const int koff = ci * 128;                       // bytes (64 bf16)
        #pragma unroll
        for (int i = 0; i < 2; i++) {
            int idx = i * 256 + tid;                     // 0..511
            int row = idx >> 3, c16 = idx & 7;
            uint32_t d = (uint32_t)(row * 144 + c16 * 16);
            const char* sa = Ahi + (size_t)(mrow0 + row) * 2048 + koff + c16 * 16;
            const char* sl = Alo + (size_t)(mrow0 + row) * 2048 + koff + c16 * 16;
            const char* sb = Bg  + (size_t)row * 4096 + koff + c16 * 16;
            CP16(S + AHI_OFF + d, sa);
            CP16(S + ALO_OFF + d, sl);
            CP16(S + BHI_OFF + d, sb);
            CP16(S + BLO_OFF + d, sb + 2048);
        }
        CP_COMMIT();
    };

    load_chunk(0, 0);
    load_chunk(1, 1);
    for (int ci = 0; ci < 16; ci++) {
        const int stg = ci % 3;
        if (ci + 1 < 16) { CP_WAIT1(); } else { CP_WAIT0(); }
        __syncthreads();
        if (ci + 2 < 16) load_chunk(ci + 2, (ci + 2) % 3);

        const uint32_t S  = sBuf + stg * STG;
        const uint32_t aH = S + AHI_OFF + aOff;
        const uint32_t aL = S + ALO_OFF + aOff;
        const uint32_t bH = S + BHI_OFF + bOff;
        const uint32_t bL = S + BLO_OFF + bOff;

        #pragma unroll
        for (int kk = 0; kk < 4; kk++) {
            uint32_t ah[2][4], al[2][4], bh[2][2], bl[2][2];
            #pragma unroll
            for (int mt = 0; mt < 2; mt++) {
                LDSM4(ah[mt], aH + mt * (16 * 144) + kk * 32);
                LDSM4(al[mt], aL + mt * (16 * 144) + kk * 32);
            }
            #pragma unroll
            for (int nt = 0; nt < 2; nt++) {
                LDSM2(bh[nt], bH + nt * (8 * 144) + kk * 32);
                LDSM2(bl[nt], bL + nt * (8 * 144) + kk * 32);
            }
            #pragma unroll
            for (int mt = 0; mt < 2; mt++)
                #pragma unroll
                for (int nt = 0; nt < 2; nt++) {
                    MMA16816(acc[mt][nt], ah[mt], bh[nt]);
                    MMA16816(acc[mt][nt], ah[mt], bl[nt]);
                    MMA16816(acc[mt][nt], al[mt], bh[nt]);
                }
        }
    }
    __syncthreads();

    // ---- epilogue: transpose via smem, gates, state update ----
    float* Csm = (float*)smem;            // [64][68]
    const int tg = lane >> 2, tq = lane & 3;
    #pragma unroll
    for (int mt = 0; mt < 2; mt++)
        #pragma unroll
        for (int nt = 0; nt < 2; nt++) {
            int r = wm * 32 + mt * 16 + tg;
            int c = wn * 16 + nt * 8 + tq * 2;
            Csm[r * 68 + c]           = acc[mt][nt][0];
            Csm[r * 68 + c + 1]       = acc[mt][nt][1];
            Csm[(r + 8) * 68 + c]     = acc[mt][nt][2];
            Csm[(r + 8) * 68 + c + 1] = acc[mt][nt][3];
        }
    __syncthreads();

    const int b_loc = tid >> 2;
    const int uq    = (tid & 3) * 4;
    const int b     = mrow0 + b_loc;
    const int tok   = tokens[b * Tn + t];
    const bool msk  = (tok != 0);
    const float* ew = g_embW + (size_t)tok * FHn;

    #pragma unroll
    for (int j = 0; j < 4; j++) {
        int ul = uq + j, u = u0 + ul;
        float zi = Csm[b_loc * 68 + ul]      + ew[u];
        float zf = Csm[b_loc * 68 + 16 + ul] + ew[Hn + u];
        float zg = Csm[b_loc * 68 + 32 + ul] + ew[2 * Hn + u];
        float zo = Csm[b_loc * 68 + 48 + ul] + ew[3 * Hn + u];

        float ig = 1.f / (1.f + expf(-zi));
        float fg = 1.f / (1.f + expf(-zf));
        float gg = tanhf(zg);
        float og = 1.f / (1.f + expf(-zo));

        float c_old = g_c[b * Hn + u];
        float h_old = g_hf[cur][b * Hn + u];
        float c_new = fg * c_old + ig * gg;
        float h_new = og * tanhf(c_new);
        float c_out = msk ? c_new : c_old;
        float h_out = msk ? h_new : h_old;

        g_c[b * Hn + u]       = c_out;
        g_hf[nxt][b * Hn + u] = h_out;
        __nv_bfloat16 hb = __float2bfloat16(h_out);
        __nv_bfloat16 lb = __float2bfloat16(h_out - __bfloat162float(hb));
        g_hbf[nxt][0][b * Hn + u] = hb;
        g_hbf[nxt][1][b * Hn + u] = lb;
        size_t srow = ((size_t)b * Tn + t) * Hn + u;
        g_shi[srow] = hb;
        g_slo[srow] = lb;
    }
}

// ============================================================
// decoder via mma.sync: logits = states @ Wd + bd, fused softmax.
// grid 512 CTAs (tile 128 rows x 128 V), warp tile 64x32, K=3072.
// 3-stage pipeline identical in structure to the step kernel
// (preload 2 groups so CP_WAIT1 guarantees stage ci is complete).
// ============================================================
#define DACH 18432       // A buffer (128*144)
#define DBCH 18432       // B buffer (128*144)
#define DSTG (DACH + DBCH)               // 36864
#define DEC_SMEM (3 * DSTG)              // 110592

__global__ __launch_bounds__(256, 1) void decoder_mma(const float* __restrict__ bd,
                                                      float* __restrict__ out) {
    extern __shared__ __align__(128) char smem[];
    const uint32_t sBuf = smem_u32(smem);

    const int tid  = threadIdx.x;
    const int lane = tid & 31;
    const int wid  = tid >> 5;
    const int wm   = wid >> 2;
    const int wn   = wid & 3;
    const size_t R0 = (size_t)blockIdx.x * 128;

    float acc[4][4][4];
    #pragma unroll
    for (int mt = 0; mt < 4; mt++)
        #pragma unroll
        for (int nt = 0; nt < 4; nt++)
            #pragma unroll
            for (int q = 0; q < 4; q++) acc[mt][nt][q] = 0.f;

    const uint32_t aOff = (uint32_t)(wm * 64 + (lane & 15)) * 144 + (uint32_t)(lane >> 4) * 16;
    const uint32_t bOff = (uint32_t)(wn * 32 + (lane & 7))  * 144 + (uint32_t)((lane >> 3) & 1) * 16;

    auto load_chunk = [&](int ci, int stg) {
        const uint32_t S = sBuf + stg * DSTG;
        const char* Asel = (ci < 16) ? (const char*)g_shi
                        : (ci < 32) ? (const char*)g_slo : (const char*)g_shi;
        int koff = (ci & 15) * 128;
        #pragma unroll
        for (int i = 0; i < 4; i++) {
            int idx = i * 256 + tid;
            int row = idx >> 3, c16 = idx & 7;
            CP16(S + row * 144 + c16 * 16,
                 Asel + (R0 + row) * 2048 + koff + c16 * 16);
        }
        #pragma unroll
        for (int i = 0; i < 4; i++) {
            int idx = i * 256 + tid;
            int row = idx >> 3, c16 = idx & 7;
            CP16(S + DACH + row * 144 + c16 * 16,
                 (const char*)&g_Wpk[0][0] + row * (KSPL * 2) + ci * 128 + c16 * 16);
        }
        CP_COMMIT();
    };

    load_chunk(0, 0);
    load_chunk(1, 1);
    for (int ci = 0; ci < 48; ci++) {
        const int stg = ci % 3;
        if (ci + 1 < 48) { CP_WAIT1(); } else { CP_WAIT0(); }
        __syncthreads();
        if (ci + 2 < 48) load_chunk(ci + 2, (ci + 2) % 3);

        const uint32_t a0 = sBuf + stg * DSTG + aOff;
        const uint32_t b0 = sBuf + stg * DSTG + DACH + bOff;
        #pragma unroll
        for (int kk = 0; kk < 4; kk++) {
            uint32_t ar[4][4], br[4][2];
            #pragma unroll
            for (int mt = 0; mt < 4; mt++) LDSM4(ar[mt], a0 + mt * (16 * 144) + kk * 32);
            #pragma unroll
            for (int nt = 0; nt < 4; nt++) LDSM2(br[nt], b0 + nt * (8 * 144) + kk * 32);
            #pragma unroll
            for (int mt = 0; mt < 4; mt++)
                #pragma unroll
                for (int nt = 0; nt < 4; nt++) MMA16816(acc[mt][nt], ar[mt], br[nt]);
        }
    }
    __syncthreads();

    // ---- epilogue: logits tile -> smem, bias + softmax, write out ----
    float* Csm = (float*)smem;            // [128][132]
    const int tg = lane >> 2, tq = lane & 3;
    #pragma unroll
    for (int mt = 0; mt < 4; mt++)
        #pragma unroll
        for (int nt = 0; nt < 4; nt++) {
            int r = wm * 64 + mt * 16 + tg;
            int c = wn * 32 + nt * 8 + tq * 2;
            Csm[r * 132 + c]           = acc[mt][nt][0];
            Csm[r * 132 + c + 1]       = acc[mt][nt][1];
            Csm[(r + 8) * 132 + c]     = acc[mt][nt][2];
            Csm[(r + 8) * 132 + c + 1] = acc[mt][nt][3];
        }
    __syncthreads();

    float4 bd4 = *reinterpret_cast<const float4*>(&bd[lane * 4]);
    #pragma unroll
    for (int rr = 0; rr < 16; rr++) {
        int row = wid * 16 + rr;
        float4 x = *reinterpret_cast<const float4*>(&Csm[row * 132 + lane * 4]);
        x.x += bd4.x; x.y += bd4.y; x.z += bd4.z; x.w += bd4.w;
        float m = fmaxf(fmaxf(x.x, x.y), fmaxf(x.z, x.w));
        #pragma unroll
        for (int o = 16; o > 0; o >>= 1) m = fmaxf(m, __shfl_xor_sync(0xffffffff, m, o));
        float4 e;
        e.x = expf(x.x - m); e.y = expf(x.y - m);
        e.z = expf(x.z - m); e.w = expf(x.w - m);
        float s = e.x + e.y + e.z + e.w;
        #pragma unroll
        for (int o = 16; o > 0; o >>= 1) s += __shfl_xor_sync(0xffffffff, s, o);
        float inv = 1.f / s;
        e.x *= inv; e.y *= inv; e.z *= inv; e.w *= inv;
        *reinterpret_cast<float4*>(&out[(R0 + row) * Vn + lane * 4]) = e;
    }
}

// ============================================================
// launcher
// ============================================================
extern "C" void kernel_launch(void* const* d_in, const int* in_sizes, int n_in,
                              void* d_out, int out_size) {
    const int*   tokens = (const int*)  d_in[0];
    const float* emb    = (const float*)d_in[1];
    const float* W      = (const float*)d_in[2];
    const float* U      = (const float*)d_in[3];
    const float* bias   = (const float*)d_in[4];
    const float* Wd     = (const float*)d_in[5];
    const float* bd     = (const float*)d_in[6];
    float*       out    = (float*)d_out;
    (void)in_sizes; (void)n_in; (void)out_size;

    cudaFuncSetAttribute(lstm_step_mma, cudaFuncAttributeMaxDynamicSharedMemorySize, STEP_SMEM);
    cudaFuncSetAttribute(decoder_mma,  cudaFuncAttributeMaxDynamicSharedMemorySize, DEC_SMEM);

    init_zero<<<128, 256>>>();
    embw_kernel<<<128, 128>>>(emb, W, bias);
    packB_kernel<<<64, 256>>>(U);
    packW_kernel<<<96, 256>>>(Wd);
    for (int t = 0; t < Tn; t++)
        lstm_step_mma<<<128, 256, STEP_SMEM>>>(tokens, t);
    decoder_mma<<<512, 256, DEC_SMEM>>>(bd, out);
}

// round 6
// speedup vs baseline: 4.5084x; 1.3204x over previous
#include <cuda_runtime.h>
#include <cuda_fp16.h>
#include <cstdint>
#include <math.h>

#define Bn  128
#define Tn  512
#define En  256
#define Hn  1024
#define FHn 4096
#define Vn  128
#define KD  2048           // decoder split-K: [states] x [Wd_hi ; Wd_lo]

// ---------------- device scratch (static: no runtime allocs) ----------------
__device__ float g_embW[Vn * FHn];                       // emb@W + b (2 MB, L2-resident)
__device__ float g_hf[2][Bn * Hn];                       // fp32 h ping-pong (exact mask-carry)
__device__ float g_c[Bn * Hn];                           // cell state
__device__ __half g_hh[2][Bn * Hn];                      // fp16 h (GEMM operand)
__device__ __half g_Bpk[64][64][2 * Hn];                 // [cid][n][k<1024: U_hi, else U_lo] (16 MB)
__device__ __half g_Wpk[Vn][KD];                         // packed Wd hi/lo (512 KB)
__device__ __half g_sh[(size_t)Bn * Tn * Hn];            // states fp16 (128 MB)

// ---------------- helpers ----------------
__device__ __forceinline__ uint32_t smem_u32(const void* p) {
    uint32_t a;
    asm("{ .reg .u64 t; cvta.to.shared.u64 t, %1; cvt.u32.u64 %0, t; }" : "=r"(a) : "l"(p));
    return a;
}
#define CP16(dst, src)  asm volatile("cp.async.cg.shared.global [%0], [%1], 16;" :: "r"(dst), "l"(src))
#define CP_COMMIT()     asm volatile("cp.async.commit_group;" ::: "memory")
#define CP_WAIT1()      asm volatile("cp.async.wait_group 1;" ::: "memory")
#define CP_WAIT0()      asm volatile("cp.async.wait_group 0;" ::: "memory")

#define LDSM4(r, addr)                                                              \
    asm volatile("ldmatrix.sync.aligned.m8n8.x4.shared.b16 {%0,%1,%2,%3}, [%4];"    \
        : "=r"((r)[0]), "=r"((r)[1]), "=r"((r)[2]), "=r"((r)[3]) : "r"(addr))
#define LDSM2(r, addr)                                                              \
    asm volatile("ldmatrix.sync.aligned.m8n8.x2.shared.b16 {%0,%1}, [%2];"          \
        : "=r"((r)[0]), "=r"((r)[1]) : "r"(addr))
#define MMA16816(d, a, b)                                                           \
    asm volatile("mma.sync.aligned.m16n8k16.row.col.f32.f16.f16.f32 "               \
        "{%0,%1,%2,%3}, {%4,%5,%6,%7}, {%8,%9}, {%0,%1,%2,%3};"                     \
        : "+f"((d)[0]), "+f"((d)[1]), "+f"((d)[2]), "+f"((d)[3])                    \
        : "r"((a)[0]), "r"((a)[1]), "r"((a)[2]), "r"((a)[3]),                       \
          "r"((b)[0]), "r"((b)[1]))

// ============================================================
// init: zero h0 (fp32 + fp16) and c0
// ============================================================
__global__ void init_zero() {
    int i = blockIdx.x * blockDim.x + threadIdx.x;      // 32768 threads
    float4 z = make_float4(0.f, 0.f, 0.f, 0.f);
    reinterpret_cast<float4*>(g_hf[0])[i] = z;
    reinterpret_cast<float4*>(g_c)[i]     = z;
    if (i < (Bn * Hn * 2) / 16)
        reinterpret_cast<uint4*>(&g_hh[0][0])[i] = make_uint4(0u, 0u, 0u, 0u);
}

// ============================================================
// embW = emb@W + b (fp32, one-time)
// ============================================================
__global__ __launch_bounds__(128) void embw_kernel(const float* __restrict__ emb,
                                                   const float* __restrict__ W,
                                                   const float* __restrict__ bias) {
    __shared__ float es[8][En];
    int tid = threadIdx.x;
    int fb  = blockIdx.x & 7;
    int vb  = blockIdx.x >> 3;
    #pragma unroll
    for (int i = 0; i < 16; i++) {
        int idx = i * 128 + tid;
        es[idx >> 8][idx & 255] = emb[(vb * 8 + (idx >> 8)) * En + (idx & 255)];
    }
    __syncthreads();
    int f0 = fb * 512 + tid * 4;
    float acc[8][4];
    #pragma unroll
    for (int v = 0; v < 8; v++)
        #pragma unroll
        for (int c = 0; c < 4; c++) acc[v][c] = 0.f;
    for (int e = 0; e < En; e++) {
        float4 w4 = *reinterpret_cast<const float4*>(&W[e * FHn + f0]);
        #pragma unroll
        for (int v = 0; v < 8; v++) {
            float a = es[v][e];
            acc[v][0] += a * w4.x; acc[v][1] += a * w4.y;
            acc[v][2] += a * w4.z; acc[v][3] += a * w4.w;
        }
    }
    float4 b4 = *reinterpret_cast<const float4*>(&bias[f0]);
    #pragma unroll
    for (int v = 0; v < 8; v++) {
        float4 r;
        r.x = acc[v][0] + b4.x; r.y = acc[v][1] + b4.y;
        r.z = acc[v][2] + b4.z; r.w = acc[v][3] + b4.w;
        *reinterpret_cast<float4*>(&g_embW[(vb * 8 + v) * FHn + f0]) = r;
    }
}

// ============================================================
// pack B: g_Bpk[cid][n][k], n = gate*16+ul; k<1024 -> U_hi(fp16), else U_lo
// ============================================================
__global__ __launch_bounds__(256) void packB_kernel(const float* __restrict__ U) {
    int cid = blockIdx.x, tid = threadIdx.x;
    int u0 = cid * 16;
    for (int i = tid; i < 64 * 2 * Hn; i += 256) {
        int n = i >> 11, k = i & (2 * Hn - 1);
        int kk  = k & (Hn - 1);
        int col = (n >> 4) * Hn + u0 + (n & 15);
        float v = U[kk * FHn + col];
        __half hi = __float2half(v);
        g_Bpk[cid][n][k] = (k < Hn) ? hi : __float2half(v - __half2float(hi));
    }
}

// ============================================================
// pack Wd: g_Wpk[v][k], k<1024 -> Wd_hi(fp16), else Wd_lo
// ============================================================
__global__ __launch_bounds__(256) void packW_kernel(const float* __restrict__ Wd) {
    int tid = blockIdx.x * 256 + threadIdx.x;
    for (int i = tid; i < Vn * KD; i += gridDim.x * 256) {
        int v = i / KD, k = i - v * KD;
        int kk = k & (Hn - 1);
        float x = Wd[kk * Vn + v];
        __half hi = __float2half(x);
        g_Wpk[v][k] = (k < Hn) ? hi : __float2half(x - __half2float(hi));
    }
}

// ============================================================
// LSTM step via fp16 mma.sync, full chip, 2 products.
// grid 128 = 2 M-halves x 64 col-tiles. CTA tile M=64, N=64, true-K=1024.
// Per macro-chunk (K=64): stage {A, B_hi, B_lo}; acc += A*B_hi + A*B_lo.
// 3-stage cp.async pipeline (preload 2 -> CP_WAIT1 drains stage ci),
// one __syncthreads per chunk. 8 warps (2 wm x 4 wn), warp tile 32x16.
// ============================================================
#define TILE  9216                       // 64 rows * 144B
#define STG   (3 * TILE)                 // 27648: A | B_hi | B_lo
#define STEP_SMEM (3 * STG)              // 82944

__global__ __launch_bounds__(256, 1) void lstm_step_mma(const int* __restrict__ tokens, int t) {
    extern __shared__ __align__(128) char smem[];
    const uint32_t sBuf = smem_u32(smem);

    const int tid  = threadIdx.x;
    const int mb   = blockIdx.x & 1;
    const int cid  = blockIdx.x >> 1;
    const int lane = tid & 31;
    const int wid  = tid >> 5;
    const int wm   = wid >> 2;            // 0..1
    const int wn   = wid & 3;             // 0..3
    const int cur  = t & 1, nxt = cur ^ 1;
    const int u0   = cid * 16;
    const int mrow0 = mb * 64;

    const char* Ag = (const char*)g_hh[cur];
    const char* Bg = (const char*)&g_Bpk[cid][0][0];

    float acc[2][2][4];
    #pragma unroll
    for (int mt = 0; mt < 2; mt++)
        #pragma unroll
        for (int nt = 0; nt < 2; nt++)
            #pragma unroll
            for (int q = 0; q < 4; q++) acc[mt][nt][q] = 0.f;

    const uint32_t aOff = (uint32_t)(wm * 32 + (lane & 15)) * 144 + (uint32_t)(lane >> 4) * 16;
    const uint32_t bOff = (uint32_t)(wn * 16 + (lane & 7))  * 144 + (uint32_t)((lane >> 3) & 1) * 16;

    auto load_chunk = [&](int ci, int stg) {
        const uint32_t S = sBuf + stg * STG;
        const int koff = ci * 128;                       // bytes (64 fp16)
        #pragma unroll
        for (int i = 0; i < 2; i++) {
            int idx = i * 256 + tid;                     // 0..511
            int row = idx >> 3, c16 = idx & 7;
            uint32_t d = (uint32_t)(row * 144 + c16 * 16);
            CP16(S + d,            Ag + (size_t)(mrow0 + row) * 2048 + koff + c16 * 16);
            const char* sb = Bg + (size_t)row * 4096 + koff + c16 * 16;
            CP16(S + TILE + d,     sb);
            CP16(S + 2 * TILE + d, sb + 2048);
        }
        CP_COMMIT();
    };

    load_chunk(0, 0);
    load_chunk(1, 1);
    for (int ci = 0; ci < 16; ci++) {
        const int stg = ci % 3;
        if (ci + 1 < 16) { CP_WAIT1(); } else { CP_WAIT0(); }
        __syncthreads();
        if (ci + 2 < 16) load_chunk(ci + 2, (ci + 2) % 3);

        const uint32_t S  = sBuf + stg * STG;
        const uint32_t aA = S + aOff;
        const uint32_t bH = S + TILE + bOff;
        const uint32_t bL = S + 2 * TILE + bOff;

        #pragma unroll
        for (int kk = 0; kk < 4; kk++) {
            uint32_t ar[2][4], bh[2][2], bl[2][2];
            #pragma unroll
            for (int mt = 0; mt < 2; mt++) LDSM4(ar[mt], aA + mt * (16 * 144) + kk * 32);
            #pragma unroll
            for (int nt = 0; nt < 2; nt++) {
                LDSM2(bh[nt], bH + nt * (8 * 144) + kk * 32);
                LDSM2(bl[nt], bL + nt * (8 * 144) + kk * 32);
            }
            #pragma unroll
            for (int mt = 0; mt < 2; mt++)
                #pragma unroll
                for (int nt = 0; nt < 2; nt++) {
                    MMA16816(acc[mt][nt], ar[mt], bh[nt]);
                    MMA16816(acc[mt][nt], ar[mt], bl[nt]);
                }
        }
    }
    __syncthreads();

    // ---- epilogue: transpose via smem, gates, state update ----
    float* Csm = (float*)smem;            // [64][68]
    const int tg = lane >> 2, tq = lane & 3;
    #pragma unroll
    for (int mt = 0; mt < 2; mt++)
        #pragma unroll
        for (int nt = 0; nt < 2; nt++) {
            int r = wm * 32 + mt * 16 + tg;
            int c = wn * 16 + nt * 8 + tq * 2;
            Csm[r * 68 + c]           = acc[mt][nt][0];
            Csm[r * 68 + c + 1]       = acc[mt][nt][1];
            Csm[(r + 8) * 68 + c]     = acc[mt][nt][2];
            Csm[(r + 8) * 68 + c + 1] = acc[mt][nt][3];
        }
    __syncthreads();

    const int b_loc = tid >> 2;
    const int uq    = (tid & 3) * 4;
    const int b     = mrow0 + b_loc;
    const int tok   = tokens[b * Tn + t];
    const bool msk  = (tok != 0);
    const float* ew = g_embW + (size_t)tok * FHn;

    #pragma unroll
    for (int j = 0; j < 4; j++) {
        int ul = uq + j, u = u0 + ul;
        float zi = Csm[b_loc * 68 + ul]      + ew[u];
        float zf = Csm[b_loc * 68 + 16 + ul] + ew[Hn + u];
        float zg = Csm[b_loc * 68 + 32 + ul] + ew[2 * Hn + u];
        float zo = Csm[b_loc * 68 + 48 + ul] + ew[3 * Hn + u];

        float ig = 1.f / (1.f + expf(-zi));
        float fg = 1.f / (1.f + expf(-zf));
        float gg = tanhf(zg);
        float og = 1.f / (1.f + expf(-zo));

        float c_old = g_c[b * Hn + u];
        float h_old = g_hf[cur][b * Hn + u];
        float c_new = fg * c_old + ig * gg;
        float h_new = og * tanhf(c_new);
        float c_out = msk ? c_new : c_old;
        float h_out = msk ? h_new : h_old;

        g_c[b * Hn + u]       = c_out;
        g_hf[nxt][b * Hn + u] = h_out;
        __half hh = __float2half(h_out);
        g_hh[nxt][b * Hn + u] = hh;
        g_sh[((size_t)b * Tn + t) * Hn + u] = hh;
    }
}

// ============================================================
// decoder via fp16 mma.sync: logits = states @ Wd + bd, fused softmax.
// grid 512 CTAs (tile 128 rows x 128 V), warp tile 64x32, K=2048
// ([states] vs [Wd_hi ; Wd_lo] concatenated along K).
// 3-stage pipeline (preload 2 groups; CP_WAIT1 drains stage ci).
// ============================================================
#define DACH 18432       // A buffer (128*144)
#define DBCH 18432       // B buffer (128*144)
#define DSTG (DACH + DBCH)               // 36864
#define DEC_SMEM (3 * DSTG)              // 110592

__global__ __launch_bounds__(256, 1) void decoder_mma(const float* __restrict__ bd,
                                                      float* __restrict__ out) {
    extern __shared__ __align__(128) char smem[];
    const uint32_t sBuf = smem_u32(smem);

    const int tid  = threadIdx.x;
    const int lane = tid & 31;
    const int wid  = tid >> 5;
    const int wm   = wid >> 2;
    const int wn   = wid & 3;
    const size_t R0 = (size_t)blockIdx.x * 128;

    float acc[4][4][4];
    #pragma unroll
    for (int mt = 0; mt < 4; mt++)
        #pragma unroll
        for (int nt = 0; nt < 4; nt++)
            #pragma unroll
            for (int q = 0; q < 4; q++) acc[mt][nt][q] = 0.f;

    const uint32_t aOff = (uint32_t)(wm * 64 + (lane & 15)) * 144 + (uint32_t)(lane >> 4) * 16;
    const uint32_t bOff = (uint32_t)(wn * 32 + (lane & 7))  * 144 + (uint32_t)((lane >> 3) & 1) * 16;

    auto load_chunk = [&](int ci, int stg) {
        const uint32_t S = sBuf + stg * DSTG;
        const int koffA = (ci & 15) * 128;   // states repeat for hi/lo halves
        const int koffB = ci * 128;          // Wpk spans full K=2048
        #pragma unroll
        for (int i = 0; i < 4; i++) {
            int idx = i * 256 + tid;
            int row = idx >> 3, c16 = idx & 7;
            CP16(S + row * 144 + c16 * 16,
                 (const char*)g_sh + (R0 + row) * 2048 + koffA + c16 * 16);
        }
        #pragma unroll
        for (int i = 0; i < 4; i++) {
            int idx = i * 256 + tid;
            int row = idx >> 3, c16 = idx & 7;
            CP16(S + DACH + row * 144 + c16 * 16,
                 (const char*)&g_Wpk[0][0] + row * (KD * 2) + koffB + c16 * 16);
        }
        CP_COMMIT();
    };

    load_chunk(0, 0);
    load_chunk(1, 1);
    for (int ci = 0; ci < 32; ci++) {
        const int stg = ci % 3;
        if (ci + 1 < 32) { CP_WAIT1(); } else { CP_WAIT0(); }
        __syncthreads();
        if (ci + 2 < 32) load_chunk(ci + 2, (ci + 2) % 3);

        const uint32_t a0 = sBuf + stg * DSTG + aOff;
        const uint32_t b0 = sBuf + stg * DSTG + DACH + bOff;
        #pragma unroll
        for (int kk = 0; kk < 4; kk++) {
            uint32_t ar[4][4], br[4][2];
            #pragma unroll
            for (int mt = 0; mt < 4; mt++) LDSM4(ar[mt], a0 + mt * (16 * 144) + kk * 32);
            #pragma unroll
            for (int nt = 0; nt < 4; nt++) LDSM2(br[nt], b0 + nt * (8 * 144) + kk * 32);
            #pragma unroll
            for (int mt = 0; mt < 4; mt++)
                #pragma unroll
                for (int nt = 0; nt < 4; nt++) MMA16816(acc[mt][nt], ar[mt], br[nt]);
        }
    }
    __syncthreads();

    // ---- epilogue: logits tile -> smem, bias + softmax, write out ----
    float* Csm = (float*)smem;            // [128][132]
    const int tg = lane >> 2, tq = lane & 3;
    #pragma unroll
    for (int mt = 0; mt < 4; mt++)
        #pragma unroll
        for (int nt = 0; nt < 4; nt++) {
            int r = wm * 64 + mt * 16 + tg;
            int c = wn * 32 + nt * 8 + tq * 2;
            Csm[r * 132 + c]           = acc[mt][nt][0];
            Csm[r * 132 + c + 1]       = acc[mt][nt][1];
            Csm[(r + 8) * 132 + c]     = acc[mt][nt][2];
            Csm[(r + 8) * 132 + c + 1] = acc[mt][nt][3];
        }
    __syncthreads();

    float4 bd4 = *reinterpret_cast<const float4*>(&bd[lane * 4]);
    #pragma unroll
    for (int rr = 0; rr < 16; rr++) {
        int row = wid * 16 + rr;
        float4 x = *reinterpret_cast<const float4*>(&Csm[row * 132 + lane * 4]);
        x.x += bd4.x; x.y += bd4.y; x.z += bd4.z; x.w += bd4.w;
        float m = fmaxf(fmaxf(x.x, x.y), fmaxf(x.z, x.w));
        #pragma unroll
        for (int o = 16; o > 0; o >>= 1) m = fmaxf(m, __shfl_xor_sync(0xffffffff, m, o));
        float4 e;
        e.x = expf(x.x - m); e.y = expf(x.y - m);
        e.z = expf(x.z - m); e.w = expf(x.w - m);
        float s = e.x + e.y + e.z + e.w;
        #pragma unroll
        for (int o = 16; o > 0; o >>= 1) s += __shfl_xor_sync(0xffffffff, s, o);
        float inv = 1.f / s;
        e.x *= inv; e.y *= inv; e.z *= inv; e.w *= inv;
        *reinterpret_cast<float4*>(&out[(R0 + row) * Vn + lane * 4]) = e;
    }
}

// ============================================================
// launcher
// ============================================================
extern "C" void kernel_launch(void* const* d_in, const int* in_sizes, int n_in,
                              void* d_out, int out_size) {
    const int*   tokens = (const int*)  d_in[0];
    const float* emb    = (const float*)d_in[1];
    const float* W      = (const float*)d_in[2];
    const float* U      = (const float*)d_in[3];
    const float* bias   = (const float*)d_in[4];
    const float* Wd     = (const float*)d_in[5];
    const float* bd     = (const float*)d_in[6];
    float*       out    = (float*)d_out;
    (void)in_sizes; (void)n_in; (void)out_size;

    cudaFuncSetAttribute(lstm_step_mma, cudaFuncAttributeMaxDynamicSharedMemorySize, STEP_SMEM);
    cudaFuncSetAttribute(decoder_mma,  cudaFuncAttributeMaxDynamicSharedMemorySize, DEC_SMEM);

    init_zero<<<128, 256>>>();
    embw_kernel<<<128, 128>>>(emb, W, bias);
    packB_kernel<<<64, 256>>>(U);
    packW_kernel<<<96, 256>>>(Wd);
    for (int t = 0; t < Tn; t++)
        lstm_step_mma<<<128, 256, STEP_SMEM>>>(tokens, t);
    decoder_mma<<<512, 256, DEC_SMEM>>>(bd, out);
}